// round 2
// baseline (speedup 1.0000x reference)
#include <cuda_runtime.h>
#include <math.h>

#define B_   1024
#define C_   1024
#define E_   128
#define H_   8
#define TC   64      // cities per tile
#define PAD  132     // padded smem row stride (floats): 16B-aligned, conflict-friendly

// Scratch (allocation-free rule: __device__ globals)
__device__ float g_qf[B_ * E_];
__device__ float g_VwT[E_ * E_];
__device__ float g_KfwT[E_ * E_];

// ---------------------------------------------------------------------------
// Kernel 0: transpose Vw, Kfw -> (k, col) layout so block smem fills coalesce.
// ---------------------------------------------------------------------------
__global__ void __launch_bounds__(256) k_transpose(const float* __restrict__ Vw,
                                                   const float* __restrict__ Kfw) {
    int i = blockIdx.x * 256 + threadIdx.x;      // 0..16383 (grid.x = 64)
    const float* src = blockIdx.y ? Kfw : Vw;
    float*       dst = blockIdx.y ? g_KfwT : g_VwT;
    int k = i >> 7, c = i & 127;
    dst[i] = src[c * E_ + k];                    // dst[k][c] = W[c][k]
}

// ---------------------------------------------------------------------------
// Kernel 1: per-batch fused  q -> (v GEMM + masked online-softmax attention)
//           -> context -> Wo -> Qf   (writes g_qf[b])
// ---------------------------------------------------------------------------
__global__ void __launch_bounds__(256) k_attn(
    const float* __restrict__ h,   const float* __restrict__ hN,
    const float* __restrict__ hpr, const float* __restrict__ h0,
    const int*   __restrict__ mask,
    const float* __restrict__ Qw,  const float* __restrict__ Qb,
    const float* __restrict__ Vb,
    const float* __restrict__ Wow, const float* __restrict__ Wob,
    const float* __restrict__ Qfw, const float* __restrict__ Qfb)
{
    const int b   = blockIdx.x;
    const int tid = threadIdx.x;

    extern __shared__ float sm[];
    float* Vw_s = sm;                 // [128][PAD]
    float* hv_s = sm + 128 * PAD;     // [64][PAD]  (h tile, then v tile)

    __shared__ float q_s[128];
    __shared__ float Vb_s[128];
    __shared__ float hc_s[384];
    __shared__ float dot_s[8][64];
    __shared__ float m_run[8], l_run[8], alpha_s[8], mnew_s[8];
    __shared__ float ctx_s[128];
    __shared__ float dec_s[128];

    // Stage VwT into smem (coalesced read, conflict-free write)
    for (int i = tid; i < E_ * E_; i += 256)
        Vw_s[(i >> 7) * PAD + (i & 127)] = g_VwT[i];

    if (tid < 128) {
        hc_s[tid]       = hN [b * E_ + tid];
        hc_s[128 + tid] = hpr[b * E_ + tid];
        hc_s[256 + tid] = h0 [b * E_ + tid];
        Vb_s[tid]       = Vb[tid];
    }
    if (tid < 8) { m_run[tid] = -3.0e38f; l_run[tid] = 0.0f; }
    __syncthreads();

    // q[e] = Qb[e] + Qw[e,:] . hc   (pre-scaled by 1/sqrt(eh)=0.25)
    if (tid < 128) {
        float a = Qb[tid];
        const float4* qr = (const float4*)(Qw + tid * 384);
        const float4* xc = (const float4*)hc_s;
        #pragma unroll 8
        for (int j = 0; j < 96; j++) {
            float4 w = qr[j], x = xc[j];
            a += w.x * x.x + w.y * x.y + w.z * x.z + w.w * x.w;
        }
        q_s[tid] = a * 0.25f;
    }
    __syncthreads();

    const int col_t = tid & 15, row_t = tid >> 4;
    const int c0 = col_t * 8, r0 = row_t * 4;
    const int hh_c = tid >> 4;        // ctx-update head (tid<128)
    const int d_hh = tid & 7;         // dot head
    const int d_c  = tid >> 3;        // dot city base (0..31)

    float ctx_acc = 0.0f;

    for (int tile = 0; tile < 16; tile++) {
        const int cbase = tile * TC;

        // stage h tile
        for (int i = tid; i < TC * E_; i += 256) {
            int r = i >> 7, e = i & 127;
            hv_s[r * PAD + e] = h[((size_t)b * C_ + cbase + r) * E_ + e];
        }
        __syncthreads();

        // v tile GEMM: 4x8 micro-tile per thread
        float acc[4][8];
        #pragma unroll
        for (int rr = 0; rr < 4; rr++)
            #pragma unroll
            for (int j = 0; j < 8; j++) acc[rr][j] = 0.0f;

        #pragma unroll 4
        for (int k = 0; k < 128; k++) {
            float4 w0 = *(const float4*)&Vw_s[k * PAD + c0];
            float4 w1 = *(const float4*)&Vw_s[k * PAD + c0 + 4];
            #pragma unroll
            for (int rr = 0; rr < 4; rr++) {
                float a = hv_s[(r0 + rr) * PAD + k];
                acc[rr][0] += a * w0.x; acc[rr][1] += a * w0.y;
                acc[rr][2] += a * w0.z; acc[rr][3] += a * w0.w;
                acc[rr][4] += a * w1.x; acc[rr][5] += a * w1.y;
                acc[rr][6] += a * w1.z; acc[rr][7] += a * w1.w;
            }
        }
        __syncthreads();   // done reading h tile

        // write v (+bias) back into hv_s
        #pragma unroll
        for (int rr = 0; rr < 4; rr++)
            #pragma unroll
            for (int j = 0; j < 8; j++)
                hv_s[(r0 + rr) * PAD + c0 + j] = acc[rr][j] + Vb_s[c0 + j];
        __syncthreads();

        // masked dots: dot[hh][c] = (q_h/4) . v_h[c]
        #pragma unroll
        for (int part = 0; part < 2; part++) {
            int c = d_c + part * 32;
            float d = 0.0f;
            #pragma unroll
            for (int e = 0; e < 16; e++)
                d += q_s[d_hh * 16 + e] * hv_s[c * PAD + d_hh * 16 + e];
            d -= (float)mask[b * C_ + cbase + c] * 1.0e8f;
            dot_s[d_hh][c] = d;
        }
        __syncthreads();

        // per-head running max
        if (tid < 8) {
            float mt = -3.0e38f;
            for (int c = 0; c < 64; c++) mt = fmaxf(mt, dot_s[tid][c]);
            float mo = m_run[tid];
            float mn = fmaxf(mo, mt);
            mnew_s[tid]  = mn;
            alpha_s[tid] = expf(mo - mn);
            m_run[tid]   = mn;
        }
        __syncthreads();

        // p = exp(dot - m_new) in place
        #pragma unroll
        for (int part = 0; part < 2; part++) {
            int c = d_c + part * 32;
            dot_s[d_hh][c] = expf(dot_s[d_hh][c] - mnew_s[d_hh]);
        }
        __syncthreads();

        if (tid < 8) {
            float s = 0.0f;
            for (int c = 0; c < 64; c++) s += dot_s[tid][c];
            l_run[tid] = l_run[tid] * alpha_s[tid] + s;
        }
        // context accumulate: thread (hh,e) = tid<128 owns ctx[tid]
        if (tid < 128) {
            float a = ctx_acc * alpha_s[hh_c];
            #pragma unroll 8
            for (int c = 0; c < 64; c++)
                a += dot_s[hh_c][c] * hv_s[c * PAD + tid];
            ctx_acc = a;
        }
        __syncthreads();
    }

    if (tid < 128) ctx_s[tid] = ctx_acc / l_run[hh_c];
    __syncthreads();

    // dec = Wow @ ctx + Wob
    if (tid < 128) {
        float a = Wob[tid];
        const float4* wr = (const float4*)(Wow + tid * 128);
        const float4* xc = (const float4*)ctx_s;
        #pragma unroll 8
        for (int k = 0; k < 32; k++) {
            float4 w = wr[k], x = xc[k];
            a += w.x * x.x + w.y * x.y + w.z * x.z + w.w * x.w;
        }
        dec_s[tid] = a;
    }
    __syncthreads();

    // qf = Qfw @ dec + Qfb
    if (tid < 128) {
        float a = Qfb[tid];
        const float4* wr = (const float4*)(Qfw + tid * 128);
        const float4* xc = (const float4*)dec_s;
        #pragma unroll 8
        for (int k = 0; k < 32; k++) {
            float4 w = wr[k], x = xc[k];
            a += w.x * x.x + w.y * x.y + w.z * x.z + w.w * x.w;
        }
        g_qf[b * 128 + tid] = a;
    }
}

// ---------------------------------------------------------------------------
// Kernel 2: kf GEMM + fused logits:  10*tanh((qf . kf)/sqrt(E)) - mask*1e8
// grid (4, 1024): each block does 4 consecutive 64-city tiles of one batch.
// ---------------------------------------------------------------------------
__global__ void __launch_bounds__(256) k_logits(
    const float* __restrict__ h,
    const int*   __restrict__ mask,
    const float* __restrict__ Kfb,
    float* __restrict__ out)
{
    const int b   = blockIdx.y;
    const int tid = threadIdx.x;

    extern __shared__ float sm[];
    float* Kw_s = sm;                 // [128][PAD]
    float* h_s  = sm + 128 * PAD;     // [64][PAD]

    __shared__ float qf_s[128];
    __shared__ float Kfb_s[128];
    __shared__ float red_s[64][17];

    for (int i = tid; i < E_ * E_; i += 256)
        Kw_s[(i >> 7) * PAD + (i & 127)] = g_KfwT[i];
    if (tid < 128) { qf_s[tid] = g_qf[b * 128 + tid]; Kfb_s[tid] = Kfb[tid]; }
    __syncthreads();

    const int col_t = tid & 15, row_t = tid >> 4;
    const int c0 = col_t * 8, r0 = row_t * 4;

    for (int t = 0; t < 4; t++) {
        const int cbase = (blockIdx.x * 4 + t) * TC;

        for (int i = tid; i < TC * E_; i += 256) {
            int r = i >> 7, e = i & 127;
            h_s[r * PAD + e] = h[((size_t)b * C_ + cbase + r) * E_ + e];
        }
        __syncthreads();

        float acc[4][8];
        #pragma unroll
        for (int rr = 0; rr < 4; rr++)
            #pragma unroll
            for (int j = 0; j < 8; j++) acc[rr][j] = 0.0f;

        #pragma unroll 4
        for (int k = 0; k < 128; k++) {
            float4 w0 = *(const float4*)&Kw_s[k * PAD + c0];
            float4 w1 = *(const float4*)&Kw_s[k * PAD + c0 + 4];
            #pragma unroll
            for (int rr = 0; rr < 4; rr++) {
                float a = h_s[(r0 + rr) * PAD + k];
                acc[rr][0] += a * w0.x; acc[rr][1] += a * w0.y;
                acc[rr][2] += a * w0.z; acc[rr][3] += a * w0.w;
                acc[rr][4] += a * w1.x; acc[rr][5] += a * w1.y;
                acc[rr][6] += a * w1.z; acc[rr][7] += a * w1.w;
            }
        }

        // partial logits: sum over this thread's 8 columns
        #pragma unroll
        for (int rr = 0; rr < 4; rr++) {
            float p = 0.0f;
            #pragma unroll
            for (int j = 0; j < 8; j++)
                p += qf_s[c0 + j] * (acc[rr][j] + Kfb_s[c0 + j]);
            red_s[r0 + rr][col_t] = p;
        }
        __syncthreads();

        if (tid < 64) {
            float s = 0.0f;
            #pragma unroll
            for (int j = 0; j < 16; j++) s += red_s[tid][j];
            float lg = s * 0.08838834764831845f;   // 1/sqrt(128)
            out[(size_t)b * C_ + cbase + tid] =
                10.0f * tanhf(lg) - (float)mask[b * C_ + cbase + tid] * 1.0e8f;
        }
        __syncthreads();
    }
}

// ---------------------------------------------------------------------------
extern "C" void kernel_launch(void* const* d_in, const int* in_sizes, int n_in,
                              void* d_out, int out_size) {
    const float* h    = (const float*)d_in[0];
    const float* hN   = (const float*)d_in[1];
    const float* hpr  = (const float*)d_in[2];
    const float* h0   = (const float*)d_in[3];
    const int*   mask = (const int*)  d_in[4];
    const float* Qw   = (const float*)d_in[5];
    const float* Qb   = (const float*)d_in[6];
    const float* Vw   = (const float*)d_in[7];
    const float* Vb   = (const float*)d_in[8];
    const float* Wow  = (const float*)d_in[9];
    const float* Wob  = (const float*)d_in[10];
    const float* Qfw  = (const float*)d_in[11];
    const float* Qfb  = (const float*)d_in[12];
    const float* Kfw  = (const float*)d_in[13];
    const float* Kfb  = (const float*)d_in[14];
    float* out = (float*)d_out;

    const int SMEM = (128 * PAD + 64 * PAD) * (int)sizeof(float);  // ~99 KB
    cudaFuncSetAttribute(k_attn,   cudaFuncAttributeMaxDynamicSharedMemorySize, SMEM);
    cudaFuncSetAttribute(k_logits, cudaFuncAttributeMaxDynamicSharedMemorySize, SMEM);

    k_transpose<<<dim3(64, 2), 256>>>(Vw, Kfw);
    k_attn<<<1024, 256, SMEM>>>(h, hN, hpr, h0, mask, Qw, Qb, Vb, Wow, Wob, Qfw, Qfb);
    k_logits<<<dim3(4, 1024), 256, SMEM>>>(h, mask, Kfb, out);
}

// round 3
// speedup vs baseline: 4.6645x; 4.6645x over previous
#include <cuda_runtime.h>
#include <math.h>

#define B_   1024
#define C_   1024
#define E_   128

// ---------------- device scratch (allocation-free rule) ----------------
__device__ float g_u[B_ * 8 * E_];        // 4 MB  per-batch per-head score vectors
__device__ float g_qb[B_ * 8];            // per-head score bias
__device__ float g_dotatt[(size_t)B_ * C_ * 8];  // 32 MB: dots, then att in place
__device__ float g_s[B_ * 8 * E_];        // 4 MB  attention-weighted h sums
__device__ float g_w[B_ * E_];            // logits matvec vector
__device__ float g_kb[B_];                // logits scalar bias

// ---------------------------------------------------------------------------
// K0: per batch — q = Qw@hc + Qb;  u[h][k] = 0.25*sum_{j in head} q[j]*Vw[j][k]
//     qb[h] = 0.25*sum q[j]*Vb[j]
// ---------------------------------------------------------------------------
__global__ void __launch_bounds__(128) k_prep(
    const float* __restrict__ hN, const float* __restrict__ hpr,
    const float* __restrict__ h0,
    const float* __restrict__ Qw, const float* __restrict__ Qb,
    const float* __restrict__ Vw, const float* __restrict__ Vb)
{
    const int b = blockIdx.x, tid = threadIdx.x;
    __shared__ float hc_s[384];
    __shared__ float q_s[128];

    hc_s[tid]       = hN [b * E_ + tid];
    hc_s[128 + tid] = hpr[b * E_ + tid];
    hc_s[256 + tid] = h0 [b * E_ + tid];
    __syncthreads();

    // q[j]
    {
        float a = Qb[tid];
        const float4* qr = (const float4*)(Qw + (size_t)tid * 384);
        const float4* xc = (const float4*)hc_s;
        #pragma unroll 8
        for (int i = 0; i < 96; i++) {
            float4 w = qr[i], x = xc[i];
            a += w.x * x.x + w.y * x.y + w.z * x.z + w.w * x.w;
        }
        q_s[tid] = a;
    }
    __syncthreads();

    // u[h][k]  (thread = k, coalesced Vw reads)
    const int k = tid;
    #pragma unroll
    for (int hh = 0; hh < 8; hh++) {
        float acc = 0.0f;
        #pragma unroll
        for (int j = 0; j < 16; j++)
            acc += q_s[hh * 16 + j] * Vw[(size_t)(hh * 16 + j) * E_ + k];
        g_u[((size_t)b * 8 + hh) * E_ + k] = 0.25f * acc;
    }
    // qb[h]
    if (tid < 8) {
        float a = 0.0f;
        #pragma unroll
        for (int j = 0; j < 16; j++)
            a += q_s[tid * 16 + j] * Vb[tid * 16 + j];
        g_qb[b * 8 + tid] = 0.25f * a;
    }
}

// ---------------------------------------------------------------------------
// K1: dots[b][c][h] = h[b,c,:] . u[b,h,:]    (warp per row group, lane=4k slice)
// ---------------------------------------------------------------------------
__global__ void __launch_bounds__(256) k_dots(const float* __restrict__ h)
{
    const int b = blockIdx.y, chunk = blockIdx.x;
    const int warp = threadIdx.x >> 5, lane = threadIdx.x & 31;

    float4 u[8];
    #pragma unroll
    for (int hh = 0; hh < 8; hh++)
        u[hh] = *(const float4*)&g_u[((size_t)b * 8 + hh) * E_ + lane * 4];

    const int c0 = chunk * 256 + warp * 32;
    const float* hb = h + (size_t)b * C_ * E_;

    float4 hv = *(const float4*)&hb[(size_t)c0 * E_ + lane * 4];
    for (int r = 0; r < 32; r++) {
        const int c = c0 + r;
        float4 nxt = hv;
        if (r < 31) nxt = *(const float4*)&hb[(size_t)(c + 1) * E_ + lane * 4];

        float p[8];
        #pragma unroll
        for (int hh = 0; hh < 8; hh++)
            p[hh] = hv.x * u[hh].x + hv.y * u[hh].y + hv.z * u[hh].z + hv.w * u[hh].w;
        #pragma unroll
        for (int off = 16; off; off >>= 1)
            #pragma unroll
            for (int hh = 0; hh < 8; hh++)
                p[hh] += __shfl_xor_sync(0xffffffffu, p[hh], off);

        float v = p[0];
        #pragma unroll
        for (int hh = 1; hh < 8; hh++) if (lane == hh) v = p[hh];
        if (lane < 8)
            g_dotatt[((size_t)b * C_ + c) * 8 + lane] = v;
        hv = nxt;
    }
}

// ---------------------------------------------------------------------------
// K2: per batch softmax over c (8 heads), in smem; writes att back in place.
// ---------------------------------------------------------------------------
__global__ void __launch_bounds__(256) k_softmax(const int* __restrict__ mask)
{
    const int b = blockIdx.x, tid = threadIdx.x;
    const int warp = tid >> 5, lane = tid & 31;

    __shared__ float ds[C_ * 8];          // 32 KB
    __shared__ float qb_s[8];
    __shared__ float wred[8][8];
    __shared__ float mh[8], lh[8];

    if (tid < 8) qb_s[tid] = g_qb[b * 8 + tid];
    __syncthreads();

    float* gb = g_dotatt + (size_t)b * C_ * 8;
    // stage + add bias + mask
    for (int i = 0; i < 4; i++) {
        int c = tid * 4 + i;
        float mv = (float)mask[b * C_ + c] * 1.0e8f;
        #pragma unroll
        for (int hh = 0; hh < 8; hh++)
            ds[c * 8 + hh] = gb[c * 8 + hh] + qb_s[hh] - mv;
    }
    __syncthreads();

    // max per head
    float mx[8];
    #pragma unroll
    for (int hh = 0; hh < 8; hh++) mx[hh] = -3.0e38f;
    for (int i = 0; i < 4; i++) {
        int c = tid * 4 + i;
        #pragma unroll
        for (int hh = 0; hh < 8; hh++) mx[hh] = fmaxf(mx[hh], ds[c * 8 + hh]);
    }
    #pragma unroll
    for (int off = 16; off; off >>= 1)
        #pragma unroll
        for (int hh = 0; hh < 8; hh++)
            mx[hh] = fmaxf(mx[hh], __shfl_xor_sync(0xffffffffu, mx[hh], off));
    if (lane == 0)
        #pragma unroll
        for (int hh = 0; hh < 8; hh++) wred[warp][hh] = mx[hh];
    __syncthreads();
    if (tid < 8) {
        float m = -3.0e38f;
        #pragma unroll
        for (int w = 0; w < 8; w++) m = fmaxf(m, wred[w][tid]);
        mh[tid] = m;
    }
    __syncthreads();

    // exp + sum
    float sm8[8];
    #pragma unroll
    for (int hh = 0; hh < 8; hh++) sm8[hh] = 0.0f;
    for (int i = 0; i < 4; i++) {
        int c = tid * 4 + i;
        #pragma unroll
        for (int hh = 0; hh < 8; hh++) {
            float p = __expf(ds[c * 8 + hh] - mh[hh]);
            ds[c * 8 + hh] = p;
            sm8[hh] += p;
        }
    }
    #pragma unroll
    for (int off = 16; off; off >>= 1)
        #pragma unroll
        for (int hh = 0; hh < 8; hh++)
            sm8[hh] += __shfl_xor_sync(0xffffffffu, sm8[hh], off);
    if (lane == 0)
        #pragma unroll
        for (int hh = 0; hh < 8; hh++) wred[warp][hh] = sm8[hh];
    __syncthreads();
    if (tid < 8) {
        float s = 0.0f;
        #pragma unroll
        for (int w = 0; w < 8; w++) s += wred[w][tid];
        lh[tid] = 1.0f / s;
    }
    __syncthreads();

    // normalize + write back
    for (int i = 0; i < 4; i++) {
        int c = tid * 4 + i;
        #pragma unroll
        for (int hh = 0; hh < 8; hh++)
            gb[c * 8 + hh] = ds[c * 8 + hh] * lh[hh];
    }
}

// ---------------------------------------------------------------------------
// K3: s[b][h][k] = sum_c att[b][c][h] * h[b][c][k]
// ---------------------------------------------------------------------------
__global__ void __launch_bounds__(256) k_wsum(const float* __restrict__ h)
{
    const int b = blockIdx.x;
    const int warp = threadIdx.x >> 5, lane = threadIdx.x & 31;

    float s[8][4];
    #pragma unroll
    for (int hh = 0; hh < 8; hh++)
        #pragma unroll
        for (int j = 0; j < 4; j++) s[hh][j] = 0.0f;

    const float* hb = h + (size_t)b * C_ * E_;
    const float* ab = g_dotatt + (size_t)b * C_ * 8;

    for (int r = 0; r < 128; r++) {
        const int c = warp * 128 + r;
        float4 hv = *(const float4*)&hb[(size_t)c * E_ + lane * 4];
        float4 a0 = *(const float4*)&ab[c * 8];
        float4 a1 = *(const float4*)&ab[c * 8 + 4];
        float av[8] = {a0.x, a0.y, a0.z, a0.w, a1.x, a1.y, a1.z, a1.w};
        #pragma unroll
        for (int hh = 0; hh < 8; hh++) {
            s[hh][0] += av[hh] * hv.x;
            s[hh][1] += av[hh] * hv.y;
            s[hh][2] += av[hh] * hv.z;
            s[hh][3] += av[hh] * hv.w;
        }
    }

    __shared__ float sm[8 * 1024];        // 32 KB
    #pragma unroll
    for (int hh = 0; hh < 8; hh++)
        #pragma unroll
        for (int j = 0; j < 4; j++)
            sm[warp * 1024 + hh * 128 + lane * 4 + j] = s[hh][j];
    __syncthreads();

    #pragma unroll
    for (int i = 0; i < 4; i++) {
        int idx = threadIdx.x + i * 256;
        float acc = 0.0f;
        #pragma unroll
        for (int w = 0; w < 8; w++) acc += sm[w * 1024 + idx];
        g_s[(size_t)b * 1024 + idx] = acc;
    }
}

// ---------------------------------------------------------------------------
// K4: per batch — ctx -> dec -> qf -> (w = Kfw^T qf, kb = qf.Kfb)
// ---------------------------------------------------------------------------
__global__ void __launch_bounds__(128) k_epilogue(
    const float* __restrict__ Vw,  const float* __restrict__ Vb,
    const float* __restrict__ Wow, const float* __restrict__ Wob,
    const float* __restrict__ Qfw, const float* __restrict__ Qfb,
    const float* __restrict__ Kfw, const float* __restrict__ Kfb)
{
    const int b = blockIdx.x, tid = threadIdx.x;
    __shared__ float s_s[1024], ctx[128], dec[128], qf[128], r2[128];

    #pragma unroll
    for (int i = 0; i < 2; i++)
        *(float4*)&s_s[tid * 8 + i * 4] =
            *(const float4*)&g_s[(size_t)b * 1024 + tid * 8 + i * 4];
    __syncthreads();

    // ctx[j] = s[head(j)] . Vw[j,:] + Vb[j]
    {
        const int head = tid >> 4;
        float a = Vb[tid];
        const float4* wr = (const float4*)(Vw + (size_t)tid * E_);
        const float4* xc = (const float4*)&s_s[head * 128];
        #pragma unroll 8
        for (int i = 0; i < 32; i++) {
            float4 w = wr[i], x = xc[i];
            a += w.x * x.x + w.y * x.y + w.z * x.z + w.w * x.w;
        }
        ctx[tid] = a;
    }
    __syncthreads();
    {
        float a = Wob[tid];
        const float4* wr = (const float4*)(Wow + (size_t)tid * E_);
        const float4* xc = (const float4*)ctx;
        #pragma unroll 8
        for (int i = 0; i < 32; i++) {
            float4 w = wr[i], x = xc[i];
            a += w.x * x.x + w.y * x.y + w.z * x.z + w.w * x.w;
        }
        dec[tid] = a;
    }
    __syncthreads();
    {
        float a = Qfb[tid];
        const float4* wr = (const float4*)(Qfw + (size_t)tid * E_);
        const float4* xc = (const float4*)dec;
        #pragma unroll 8
        for (int i = 0; i < 32; i++) {
            float4 w = wr[i], x = xc[i];
            a += w.x * x.x + w.y * x.y + w.z * x.z + w.w * x.w;
        }
        qf[tid] = a;
    }
    __syncthreads();

    // w[k] = sum_j qf[j] * Kfw[j][k]   (coalesced over k)
    {
        float a = 0.0f;
        #pragma unroll 8
        for (int j = 0; j < 128; j++)
            a += qf[j] * Kfw[(size_t)j * E_ + tid];
        g_w[b * 128 + tid] = a;
    }
    // kb = sum_j qf[j]*Kfb[j]
    r2[tid] = qf[tid] * Kfb[tid];
    __syncthreads();
    for (int st = 64; st; st >>= 1) {
        if (tid < st) r2[tid] += r2[tid + st];
        __syncthreads();
    }
    if (tid == 0) g_kb[b] = r2[0];
}

// ---------------------------------------------------------------------------
// K5: logits[b][c] = 10*tanh((h . w + kb)/sqrt(E)) - mask*1e8
// ---------------------------------------------------------------------------
__global__ void __launch_bounds__(256) k_logits(
    const float* __restrict__ h, const int* __restrict__ mask,
    float* __restrict__ out)
{
    const int b = blockIdx.x;
    const int warp = threadIdx.x >> 5, lane = threadIdx.x & 31;

    float4 w4 = *(const float4*)&g_w[b * 128 + lane * 4];
    float kb = g_kb[b];
    const float* hb = h + (size_t)b * C_ * E_;

    const int c0 = warp * 128;
    float4 hv = *(const float4*)&hb[(size_t)c0 * E_ + lane * 4];
    for (int r = 0; r < 128; r++) {
        const int c = c0 + r;
        float4 nxt = hv;
        if (r < 127) nxt = *(const float4*)&hb[(size_t)(c + 1) * E_ + lane * 4];

        float p = hv.x * w4.x + hv.y * w4.y + hv.z * w4.z + hv.w * w4.w;
        #pragma unroll
        for (int off = 16; off; off >>= 1)
            p += __shfl_xor_sync(0xffffffffu, p, off);

        if (lane == 0) {
            float lg = (p + kb) * 0.08838834764831845f;
            out[(size_t)b * C_ + c] =
                10.0f * tanhf(lg) - (float)mask[b * C_ + c] * 1.0e8f;
        }
        hv = nxt;
    }
}

// ---------------------------------------------------------------------------
extern "C" void kernel_launch(void* const* d_in, const int* in_sizes, int n_in,
                              void* d_out, int out_size) {
    const float* h    = (const float*)d_in[0];
    const float* hN   = (const float*)d_in[1];
    const float* hpr  = (const float*)d_in[2];
    const float* h0   = (const float*)d_in[3];
    const int*   mask = (const int*)  d_in[4];
    const float* Qw   = (const float*)d_in[5];
    const float* Qb   = (const float*)d_in[6];
    const float* Vw   = (const float*)d_in[7];
    const float* Vb   = (const float*)d_in[8];
    const float* Wow  = (const float*)d_in[9];
    const float* Wob  = (const float*)d_in[10];
    const float* Qfw  = (const float*)d_in[11];
    const float* Qfb  = (const float*)d_in[12];
    const float* Kfw  = (const float*)d_in[13];
    const float* Kfb  = (const float*)d_in[14];
    float* out = (float*)d_out;

    k_prep    <<<B_, 128>>>(hN, hpr, h0, Qw, Qb, Vw, Vb);
    k_dots    <<<dim3(4, B_), 256>>>(h);
    k_softmax <<<B_, 256>>>(mask);
    k_wsum    <<<B_, 256>>>(h);
    k_epilogue<<<B_, 128>>>(Vw, Vb, Wow, Wob, Qfw, Qfb, Kfw, Kfb);
    k_logits  <<<B_, 256>>>(h, mask, out);
}

// round 4
// speedup vs baseline: 6.2275x; 1.3351x over previous
#include <cuda_runtime.h>
#include <math.h>

#define B_    1024
#define C_    1024
#define E_    128
#define SPLIT 4
#define RPB   (C_ / SPLIT)    // 256 rows per fused block
#define TILE  64
#define NT    (RPB / TILE)    // 4 tiles

// ---------------- device scratch (allocation-free rule) ----------------
__device__ float g_u [B_ * 8 * E_];          // per-batch per-head score vectors (0.25 folded)
__device__ float g_qb[B_ * 8];               // per-head score bias (0.25 folded)
__device__ float g_pm[B_ * SPLIT * 8];       // partial max
__device__ float g_pl[B_ * SPLIT * 8];       // partial sum-exp
__device__ float g_ps[B_ * SPLIT * 8 * E_];  // partial weighted h sums
__device__ float g_w [B_ * E_];              // logits matvec vector
__device__ float g_kb[B_];                   // logits scalar bias

// ---------------------------------------------------------------------------
// K0: per batch — q = Qw@hc + Qb;  u[h][:] = 0.25 * q_h^T Vw_h ;  qb[h] = 0.25 q_h.Vb_h
// ---------------------------------------------------------------------------
__global__ void __launch_bounds__(128) k_prep(
    const float* __restrict__ hN, const float* __restrict__ hpr,
    const float* __restrict__ h0,
    const float* __restrict__ Qw, const float* __restrict__ Qb,
    const float* __restrict__ Vw, const float* __restrict__ Vb)
{
    const int b = blockIdx.x, tid = threadIdx.x;
    __shared__ float hc_s[384];
    __shared__ float q_s[128];

    hc_s[tid]       = hN [b * E_ + tid];
    hc_s[128 + tid] = hpr[b * E_ + tid];
    hc_s[256 + tid] = h0 [b * E_ + tid];
    __syncthreads();

    {
        float a = Qb[tid];
        const float4* qr = (const float4*)(Qw + (size_t)tid * 384);
        const float4* xc = (const float4*)hc_s;
        #pragma unroll 8
        for (int i = 0; i < 96; i++) {
            float4 w = qr[i], x = xc[i];
            a += w.x * x.x + w.y * x.y + w.z * x.z + w.w * x.w;
        }
        q_s[tid] = a;
    }
    __syncthreads();

    const int k = tid;
    #pragma unroll
    for (int hh = 0; hh < 8; hh++) {
        float acc = 0.0f;
        #pragma unroll
        for (int j = 0; j < 16; j++)
            acc += q_s[hh * 16 + j] * Vw[(size_t)(hh * 16 + j) * E_ + k];
        g_u[((size_t)b * 8 + hh) * E_ + k] = 0.25f * acc;
    }
    if (tid < 8) {
        float a = 0.0f;
        #pragma unroll
        for (int j = 0; j < 16; j++)
            a += q_s[tid * 16 + j] * Vb[tid * 16 + j];
        g_qb[b * 8 + tid] = 0.25f * a;
    }
}

// ---------------------------------------------------------------------------
// K1: fused dots + online softmax + weighted-sum over a 256-row slab.
// Writes partial (m, l, s[8][128]) per (batch, part).
// ---------------------------------------------------------------------------
__global__ void __launch_bounds__(256) k_fused(const float* __restrict__ h,
                                               const int*   __restrict__ mask)
{
    const int b = blockIdx.y, part = blockIdx.x;
    const int tid = threadIdx.x, warp = tid >> 5, lane = tid & 31;

    __shared__ float h_s[TILE * 132];      // 33.8 KB, padded rows
    __shared__ float p_s[TILE * 12];       // dot/p values, [c][head] pad-12
    __shared__ float mask_s[TILE];
    __shared__ float qb_s[8];
    __shared__ float m_s[8], l_s[8], al_s[8];

    // u slices in registers (lane owns e = lane*4 .. +3)
    float4 u[8];
    #pragma unroll
    for (int hh = 0; hh < 8; hh++)
        u[hh] = *(const float4*)&g_u[((size_t)b * 8 + hh) * E_ + lane * 4];

    if (tid < 8) { qb_s[tid] = g_qb[b * 8 + tid]; m_s[tid] = -3.0e38f; l_s[tid] = 0.0f; }

    float s[8];
    #pragma unroll
    for (int hh = 0; hh < 8; hh++) s[hh] = 0.0f;

    const int kk    = tid & 127;           // owned embed index
    const int chalf = tid >> 7;            // c sub-range (0/1) within tile
    const float* hb = h + ((size_t)b * C_ + part * RPB) * E_;
    const int*   mb = mask + b * C_ + part * RPB;

    for (int t = 0; t < NT; t++) {
        const int rbase = t * TILE;
        __syncthreads();                   // h_s/p_s free for reuse

        // stage h tile (coalesced float4)
        #pragma unroll
        for (int i = 0; i < 8; i++) {
            int idx = tid + i * 256;       // 2048 float4 slots
            int r = idx >> 5, e4 = idx & 31;
            *(float4*)&h_s[r * 132 + e4 * 4] =
                *(const float4*)&hb[(size_t)(rbase + r) * E_ + e4 * 4];
        }
        if (tid < TILE) mask_s[tid] = (float)mb[rbase + tid] * 1.0e8f;
        __syncthreads();

        // dots: warp w handles rows w*8 .. w*8+7
        #pragma unroll 2
        for (int rr = 0; rr < 8; rr++) {
            const int row = warp * 8 + rr;
            float4 hv = *(const float4*)&h_s[row * 132 + lane * 4];
            float p[8];
            #pragma unroll
            for (int hh = 0; hh < 8; hh++)
                p[hh] = hv.x * u[hh].x + hv.y * u[hh].y + hv.z * u[hh].z + hv.w * u[hh].w;
            #pragma unroll
            for (int off = 16; off >= 4; off >>= 1)
                #pragma unroll
                for (int hh = 0; hh < 8; hh++)
                    p[hh] += __shfl_xor_sync(0xffffffffu, p[hh], off);
            // lane group of 4 owns head lane>>2; finish reduction across mod-4 classes
            const int myh = lane >> 2;
            float v = p[0];
            #pragma unroll
            for (int hh = 1; hh < 8; hh++) if (myh == hh) v = p[hh];
            v += __shfl_xor_sync(0xffffffffu, v, 1);
            v += __shfl_xor_sync(0xffffffffu, v, 2);
            if ((lane & 3) == 0)
                p_s[row * 12 + myh] = v + qb_s[myh] - mask_s[row];
        }
        __syncthreads();

        // online softmax update: warp == head
        {
            const int hh = warp;
            float d0 = p_s[lane * 12 + hh];
            float d1 = p_s[(lane + 32) * 12 + hh];
            float mt = fmaxf(d0, d1);
            #pragma unroll
            for (int off = 16; off; off >>= 1)
                mt = fmaxf(mt, __shfl_xor_sync(0xffffffffu, mt, off));
            float mo = m_s[hh];
            float mn = fmaxf(mo, mt);
            float alpha = __expf(mo - mn);
            float p0 = __expf(d0 - mn), p1 = __expf(d1 - mn);
            p_s[lane * 12 + hh] = p0;
            p_s[(lane + 32) * 12 + hh] = p1;
            float su = p0 + p1;
            #pragma unroll
            for (int off = 16; off; off >>= 1)
                su += __shfl_xor_sync(0xffffffffu, su, off);
            if (lane == 0) { m_s[hh] = mn; l_s[hh] = l_s[hh] * alpha + su; al_s[hh] = alpha; }
        }
        __syncthreads();

        // rescale + accumulate s over this tile's c sub-range
        {
            #pragma unroll
            for (int hh = 0; hh < 8; hh++) s[hh] *= al_s[hh];
            const int c0 = chalf * 32;
            #pragma unroll 4
            for (int c = c0; c < c0 + 32; c++) {
                float  hv = h_s[c * 132 + kk];
                float4 pa = *(const float4*)&p_s[c * 12];
                float4 pb = *(const float4*)&p_s[c * 12 + 4];
                s[0] += pa.x * hv; s[1] += pa.y * hv; s[2] += pa.z * hv; s[3] += pa.w * hv;
                s[4] += pb.x * hv; s[5] += pb.y * hv; s[6] += pb.z * hv; s[7] += pb.w * hv;
            }
        }
    }
    __syncthreads();

    // combine the two c-half partial s via smem, write block partials
    if (chalf == 1) {
        #pragma unroll
        for (int hh = 0; hh < 8; hh++) h_s[hh * 128 + kk] = s[hh];
    }
    __syncthreads();
    if (chalf == 0) {
        const size_t base = (size_t)(b * SPLIT + part) * 8 * E_;
        #pragma unroll
        for (int hh = 0; hh < 8; hh++)
            g_ps[base + hh * E_ + kk] = s[hh] + h_s[hh * 128 + kk];
    }
    if (tid < 8) {
        g_pm[(b * SPLIT + part) * 8 + tid] = m_s[tid];
        g_pl[(b * SPLIT + part) * 8 + tid] = l_s[tid];
    }
}

// ---------------------------------------------------------------------------
// K2: per batch — combine partials -> sbar -> ctx -> dec -> qf -> (w, kb)
// ---------------------------------------------------------------------------
__global__ void __launch_bounds__(128) k_epilogue(
    const float* __restrict__ Vw,  const float* __restrict__ Vb,
    const float* __restrict__ Wow, const float* __restrict__ Wob,
    const float* __restrict__ Qfw, const float* __restrict__ Qfb,
    const float* __restrict__ Kfw, const float* __restrict__ Kfb)
{
    const int b = blockIdx.x, tid = threadIdx.x;
    __shared__ float sbar[1024], ctx[128], dec[128], qf[128], r2[128];
    __shared__ float ef[SPLIT][8], invl[8];

    if (tid < 8) {
        float mp[SPLIT], lp[SPLIT], m = -3.0e38f;
        #pragma unroll
        for (int p = 0; p < SPLIT; p++) {
            mp[p] = g_pm[(b * SPLIT + p) * 8 + tid];
            lp[p] = g_pl[(b * SPLIT + p) * 8 + tid];
            m = fmaxf(m, mp[p]);
        }
        float L = 0.0f;
        #pragma unroll
        for (int p = 0; p < SPLIT; p++) {
            float e = __expf(mp[p] - m);
            ef[p][tid] = e;
            L += lp[p] * e;
        }
        invl[tid] = 1.0f / L;
    }
    __syncthreads();

    #pragma unroll
    for (int hh = 0; hh < 8; hh++) {
        float a = 0.0f;
        #pragma unroll
        for (int p = 0; p < SPLIT; p++)
            a += g_ps[(size_t)((b * SPLIT + p) * 8 + hh) * E_ + tid] * ef[p][hh];
        sbar[hh * 128 + tid] = a * invl[hh];
    }
    __syncthreads();

    // ctx[j] = sbar[head(j)] . Vw[j,:] + Vb[j]
    {
        const int head = tid >> 4;
        float a = Vb[tid];
        const float4* wr = (const float4*)(Vw + (size_t)tid * E_);
        const float4* xc = (const float4*)&sbar[head * 128];
        #pragma unroll 8
        for (int i = 0; i < 32; i++) {
            float4 w = wr[i], x = xc[i];
            a += w.x * x.x + w.y * x.y + w.z * x.z + w.w * x.w;
        }
        ctx[tid] = a;
    }
    __syncthreads();
    {
        float a = Wob[tid];
        const float4* wr = (const float4*)(Wow + (size_t)tid * E_);
        const float4* xc = (const float4*)ctx;
        #pragma unroll 8
        for (int i = 0; i < 32; i++) {
            float4 w = wr[i], x = xc[i];
            a += w.x * x.x + w.y * x.y + w.z * x.z + w.w * x.w;
        }
        dec[tid] = a;
    }
    __syncthreads();
    {
        float a = Qfb[tid];
        const float4* wr = (const float4*)(Qfw + (size_t)tid * E_);
        const float4* xc = (const float4*)dec;
        #pragma unroll 8
        for (int i = 0; i < 32; i++) {
            float4 w = wr[i], x = xc[i];
            a += w.x * x.x + w.y * x.y + w.z * x.z + w.w * x.w;
        }
        qf[tid] = a;
    }
    __syncthreads();

    {   // w[k] = sum_j qf[j] * Kfw[j][k]
        float a = 0.0f;
        #pragma unroll 8
        for (int j = 0; j < 128; j++)
            a += qf[j] * Kfw[(size_t)j * E_ + tid];
        g_w[b * 128 + tid] = a;
    }
    r2[tid] = qf[tid] * Kfb[tid];
    __syncthreads();
    for (int st = 64; st; st >>= 1) {
        if (tid < st) r2[tid] += r2[tid + st];
        __syncthreads();
    }
    if (tid == 0) g_kb[b] = r2[0];
}

// ---------------------------------------------------------------------------
// K3: logits[b][c] = 10*tanh((h.w + kb)/sqrt(E)) - mask*1e8
// ---------------------------------------------------------------------------
__global__ void __launch_bounds__(256) k_logits(
    const float* __restrict__ h, const int* __restrict__ mask,
    float* __restrict__ out)
{
    const int b = blockIdx.y, chunk = blockIdx.x;
    const int warp = threadIdx.x >> 5, lane = threadIdx.x & 31;

    float4 w4 = *(const float4*)&g_w[b * 128 + lane * 4];
    float  kb = g_kb[b];
    const float* hb = h + (size_t)b * C_ * E_;

    const int c0 = chunk * 256 + warp * 32;
    float4 hv = *(const float4*)&hb[(size_t)c0 * E_ + lane * 4];
    for (int r = 0; r < 32; r++) {
        const int c = c0 + r;
        float4 nxt = hv;
        if (r < 31) nxt = *(const float4*)&hb[(size_t)(c + 1) * E_ + lane * 4];

        float p = hv.x * w4.x + hv.y * w4.y + hv.z * w4.z + hv.w * w4.w;
        #pragma unroll
        for (int off = 16; off; off >>= 1)
            p += __shfl_xor_sync(0xffffffffu, p, off);

        if (lane == 0) {
            float lg = (p + kb) * 0.08838834764831845f;   // 1/sqrt(128)
            out[(size_t)b * C_ + c] =
                10.0f * tanhf(lg) - (float)mask[b * C_ + c] * 1.0e8f;
        }
        hv = nxt;
    }
}

// ---------------------------------------------------------------------------
extern "C" void kernel_launch(void* const* d_in, const int* in_sizes, int n_in,
                              void* d_out, int out_size) {
    const float* h    = (const float*)d_in[0];
    const float* hN   = (const float*)d_in[1];
    const float* hpr  = (const float*)d_in[2];
    const float* h0   = (const float*)d_in[3];
    const int*   mask = (const int*)  d_in[4];
    const float* Qw   = (const float*)d_in[5];
    const float* Qb   = (const float*)d_in[6];
    const float* Vw   = (const float*)d_in[7];
    const float* Vb   = (const float*)d_in[8];
    const float* Wow  = (const float*)d_in[9];
    const float* Wob  = (const float*)d_in[10];
    const float* Qfw  = (const float*)d_in[11];
    const float* Qfb  = (const float*)d_in[12];
    const float* Kfw  = (const float*)d_in[13];
    const float* Kfb  = (const float*)d_in[14];
    float* out = (float*)d_out;

    k_prep    <<<B_, 128>>>(hN, hpr, h0, Qw, Qb, Vw, Vb);
    k_fused   <<<dim3(SPLIT, B_), 256>>>(h, mask);
    k_epilogue<<<B_, 128>>>(Vw, Vb, Wow, Wob, Qfw, Qfb, Kfw, Kfb);
    k_logits  <<<dim3(4, B_), 256>>>(h, mask, out);
}

// round 5
// speedup vs baseline: 6.9232x; 1.1117x over previous
#include <cuda_runtime.h>
#include <math.h>

#define B_    1024
#define C_    1024
#define E_    128
#define SPLIT 2
#define RPB   (C_ / SPLIT)    // 512 rows per fused block
#define RPW   (RPB / 8)       // 64 rows per warp

// ---------------- device scratch (allocation-free rule) ----------------
__device__ float g_u [B_ * 8 * E_];          // per-batch per-head score vectors (0.25 folded)
__device__ float g_qb[B_ * 8];               // per-head score bias (0.25 folded)
__device__ float g_pl[B_ * SPLIT * 8];       // partial sum-exp
__device__ float g_ps[B_ * SPLIT * 8 * E_];  // partial weighted h sums
__device__ float g_w [B_ * E_];              // logits matvec vector
__device__ float g_kb[B_];                   // logits scalar bias

// ---------------------------------------------------------------------------
// K0: per batch — q = Qw@hc + Qb;  u[h][:] = 0.25 * q_h^T Vw_h ;  qb[h] = 0.25 q_h.Vb_h
// ---------------------------------------------------------------------------
__global__ void __launch_bounds__(128) k_prep(
    const float* __restrict__ hN, const float* __restrict__ hpr,
    const float* __restrict__ h0,
    const float* __restrict__ Qw, const float* __restrict__ Qb,
    const float* __restrict__ Vw, const float* __restrict__ Vb)
{
    const int b = blockIdx.x, tid = threadIdx.x;
    __shared__ float hc_s[384];
    __shared__ float q_s[128];

    hc_s[tid]       = hN [b * E_ + tid];
    hc_s[128 + tid] = hpr[b * E_ + tid];
    hc_s[256 + tid] = h0 [b * E_ + tid];
    __syncthreads();

    {
        float a = Qb[tid];
        const float4* qr = (const float4*)(Qw + (size_t)tid * 384);
        const float4* xc = (const float4*)hc_s;
        #pragma unroll 8
        for (int i = 0; i < 96; i++) {
            float4 w = qr[i], x = xc[i];
            a += w.x * x.x + w.y * x.y + w.z * x.z + w.w * x.w;
        }
        q_s[tid] = a;
    }
    __syncthreads();

    const int k = tid;
    #pragma unroll
    for (int hh = 0; hh < 8; hh++) {
        float acc = 0.0f;
        #pragma unroll
        for (int j = 0; j < 16; j++)
            acc += q_s[hh * 16 + j] * Vw[(size_t)(hh * 16 + j) * E_ + k];
        g_u[((size_t)b * 8 + hh) * E_ + k] = 0.25f * acc;
    }
    if (tid < 8) {
        float a = 0.0f;
        #pragma unroll
        for (int j = 0; j < 16; j++)
            a += q_s[tid * 16 + j] * Vb[tid * 16 + j];
        g_qb[b * 8 + tid] = 0.25f * a;
    }
}

// ---------------------------------------------------------------------------
// K1: streaming dots + exp (no max shift) + weighted sums. Warp-independent.
// ---------------------------------------------------------------------------
__global__ void __launch_bounds__(256) k_fused(const float* __restrict__ h,
                                               const int*   __restrict__ mask)
{
    const int b = blockIdx.y, part = blockIdx.x;
    const int tid = threadIdx.x, warp = tid >> 5, lane = tid & 31;

    // u slices in registers (lane owns e = lane*4 .. +3)
    float4 u[8];
    #pragma unroll
    for (int hh = 0; hh < 8; hh++)
        u[hh] = *(const float4*)&g_u[((size_t)b * 8 + hh) * E_ + lane * 4];
    const float qbr = g_qb[b * 8 + (lane >> 2)];

    float4 s[8];
    #pragma unroll
    for (int hh = 0; hh < 8; hh++) s[hh] = make_float4(0.f, 0.f, 0.f, 0.f);
    float l_acc = 0.0f;

    // warp streams rows  c = part*RPB + warp + 8*i
    const float* rp = h + ((size_t)b * C_ + part * RPB + warp) * E_ + lane * 4;
    const int*   mp = mask + b * C_ + part * RPB + warp;
    const size_t rstride = (size_t)8 * E_;

    float4 h0v = *(const float4*)rp;
    float4 h1v = *(const float4*)(rp + rstride);
    int    m0  = mp[0];
    int    m1  = mp[8];

    const bool hi4 = (lane & 16) != 0;
    const bool hi3 = (lane & 8)  != 0;
    const bool hi2 = (lane & 4)  != 0;

    #pragma unroll 2
    for (int i = 0; i < RPW; i++) {
        float4 cur = h0v; int mc = m0;
        h0v = h1v; m0 = m1;
        if (i < RPW - 2) {
            h1v = *(const float4*)(rp + (size_t)(i + 2) * rstride);
            m1  = mp[(i + 2) * 8];
        }

        // per-lane partial dots for all 8 heads
        float d[8];
        #pragma unroll
        for (int hh = 0; hh < 8; hh++)
            d[hh] = cur.x * u[hh].x + cur.y * u[hh].y + cur.z * u[hh].z + cur.w * u[hh].w;

        // head-folding butterfly: 9 shfl total, lane ends with head (lane>>2)
        #pragma unroll
        for (int j = 0; j < 4; j++) {
            float send = hi4 ? d[j] : d[j + 4];
            float keep = hi4 ? d[j + 4] : d[j];
            d[j] = keep + __shfl_xor_sync(0xffffffffu, send, 16);
        }
        #pragma unroll
        for (int j = 0; j < 2; j++) {
            float send = hi3 ? d[j] : d[j + 2];
            float keep = hi3 ? d[j + 2] : d[j];
            d[j] = keep + __shfl_xor_sync(0xffffffffu, send, 8);
        }
        float send = hi2 ? d[0] : d[1];
        float keep = hi2 ? d[1] : d[0];
        float dd = keep + __shfl_xor_sync(0xffffffffu, send, 4);
        dd += __shfl_xor_sync(0xffffffffu, dd, 2);
        dd += __shfl_xor_sync(0xffffffffu, dd, 1);

        // p for this lane's head (shift-free exp: masked -> exact 0 underflow)
        float p = __expf(dd + qbr - (float)mc * 1.0e8f);
        l_acc += p;

        // broadcast all 8 head probs, accumulate weighted sums
        #pragma unroll
        for (int hh = 0; hh < 8; hh++) {
            float pb = __shfl_sync(0xffffffffu, p, hh << 2);
            s[hh].x += pb * cur.x; s[hh].y += pb * cur.y;
            s[hh].z += pb * cur.z; s[hh].w += pb * cur.w;
        }
    }

    // combine 8 warps
    __shared__ float sm[8 * 8 * 128];     // [warp][h][e] = 32 KB
    __shared__ float sl[8][8];
    #pragma unroll
    for (int hh = 0; hh < 8; hh++)
        *(float4*)&sm[warp * 1024 + hh * 128 + lane * 4] = s[hh];
    if ((lane & 3) == 0) sl[warp][lane >> 2] = l_acc;
    __syncthreads();

    const size_t base = (size_t)(b * SPLIT + part) * 8 * E_;
    #pragma unroll
    for (int k = 0; k < 4; k++) {
        int idx = tid + k * 256;
        float a = 0.0f;
        #pragma unroll
        for (int w = 0; w < 8; w++) a += sm[w * 1024 + idx];
        g_ps[base + idx] = a;
    }
    if (tid < 8) {
        float a = 0.0f;
        #pragma unroll
        for (int w = 0; w < 8; w++) a += sl[w][tid];
        g_pl[(b * SPLIT + part) * 8 + tid] = a;
    }
}

// ---------------------------------------------------------------------------
// K2: per batch — combine partials -> sbar -> ctx -> dec -> qf -> (w, kb)
// ---------------------------------------------------------------------------
__global__ void __launch_bounds__(128) k_epilogue(
    const float* __restrict__ Vw,  const float* __restrict__ Vb,
    const float* __restrict__ Wow, const float* __restrict__ Wob,
    const float* __restrict__ Qfw, const float* __restrict__ Qfb,
    const float* __restrict__ Kfw, const float* __restrict__ Kfb)
{
    const int b = blockIdx.x, tid = threadIdx.x;
    __shared__ float sbar[1024], ctx[128], dec[128], qf[128], r2[128];
    __shared__ float invl[8];

    if (tid < 8)
        invl[tid] = 1.0f / (g_pl[(b * SPLIT) * 8 + tid] + g_pl[(b * SPLIT + 1) * 8 + tid]);
    __syncthreads();

    #pragma unroll
    for (int hh = 0; hh < 8; hh++) {
        float a = g_ps[(size_t)(b * SPLIT) * 8 * E_ + hh * E_ + tid]
                + g_ps[(size_t)(b * SPLIT + 1) * 8 * E_ + hh * E_ + tid];
        sbar[hh * 128 + tid] = a * invl[hh];
    }
    __syncthreads();

    // ctx[j] = sbar[head(j)] . Vw[j,:] + Vb[j]
    {
        const int head = tid >> 4;
        float a = Vb[tid];
        const float4* wr = (const float4*)(Vw + (size_t)tid * E_);
        const float4* xc = (const float4*)&sbar[head * 128];
        #pragma unroll 8
        for (int i = 0; i < 32; i++) {
            float4 w = wr[i], x = xc[i];
            a += w.x * x.x + w.y * x.y + w.z * x.z + w.w * x.w;
        }
        ctx[tid] = a;
    }
    __syncthreads();
    {
        float a = Wob[tid];
        const float4* wr = (const float4*)(Wow + (size_t)tid * E_);
        const float4* xc = (const float4*)ctx;
        #pragma unroll 8
        for (int i = 0; i < 32; i++) {
            float4 w = wr[i], x = xc[i];
            a += w.x * x.x + w.y * x.y + w.z * x.z + w.w * x.w;
        }
        dec[tid] = a;
    }
    __syncthreads();
    {
        float a = Qfb[tid];
        const float4* wr = (const float4*)(Qfw + (size_t)tid * E_);
        const float4* xc = (const float4*)dec;
        #pragma unroll 8
        for (int i = 0; i < 32; i++) {
            float4 w = wr[i], x = xc[i];
            a += w.x * x.x + w.y * x.y + w.z * x.z + w.w * x.w;
        }
        qf[tid] = a;
    }
    __syncthreads();

    {   // w[k] = sum_j qf[j] * Kfw[j][k]
        float a = 0.0f;
        #pragma unroll 8
        for (int j = 0; j < 128; j++)
            a += qf[j] * Kfw[(size_t)j * E_ + tid];
        g_w[b * 128 + tid] = a;
    }
    r2[tid] = qf[tid] * Kfb[tid];
    __syncthreads();
    for (int st = 64; st; st >>= 1) {
        if (tid < st) r2[tid] += r2[tid + st];
        __syncthreads();
    }
    if (tid == 0) g_kb[b] = r2[0];
}

// ---------------------------------------------------------------------------
// K3: logits[b][c] = 10*tanh((h.w + kb)/sqrt(E)) - mask*1e8  (paired-row fold)
// ---------------------------------------------------------------------------
__global__ void __launch_bounds__(256) k_logits(
    const float* __restrict__ h, const int* __restrict__ mask,
    float* __restrict__ out)
{
    const int b = blockIdx.y, chunk = blockIdx.x;
    const int warp = threadIdx.x >> 5, lane = threadIdx.x & 31;

    float4 w4 = *(const float4*)&g_w[b * 128 + lane * 4];
    float  kb = g_kb[b];

    const int c0 = chunk * 256 + warp * 32;       // warp handles 32 rows (16 pairs)
    const float* rp = h + ((size_t)b * C_ + c0) * E_ + lane * 4;
    const bool hi = (lane & 16) != 0;
    const int  sub = lane >> 4;                   // 0 -> even row, 1 -> odd row

    float4 a0 = *(const float4*)rp;
    float4 a1 = *(const float4*)(rp + E_);

    #pragma unroll 2
    for (int j = 0; j < 16; j++) {
        float4 r0 = a0, r1 = a1;
        if (j < 15) {
            a0 = *(const float4*)(rp + (size_t)(2 * j + 2) * E_);
            a1 = *(const float4*)(rp + (size_t)(2 * j + 3) * E_);
        }
        float p0 = r0.x * w4.x + r0.y * w4.y + r0.z * w4.z + r0.w * w4.w;
        float p1 = r1.x * w4.x + r1.y * w4.y + r1.z * w4.z + r1.w * w4.w;

        float send = hi ? p0 : p1;
        float keep = hi ? p1 : p0;
        float t = keep + __shfl_xor_sync(0xffffffffu, send, 16);
        t += __shfl_xor_sync(0xffffffffu, t, 8);
        t += __shfl_xor_sync(0xffffffffu, t, 4);
        t += __shfl_xor_sync(0xffffffffu, t, 2);
        t += __shfl_xor_sync(0xffffffffu, t, 1);
        // lane 0 holds even-row sum, lane 16 holds odd-row sum

        if ((lane & 15) == 0) {
            int c = c0 + 2 * j + sub;
            float lg = (t + kb) * 0.08838834764831845f;   // 1/sqrt(128)
            out[(size_t)b * C_ + c] =
                10.0f * tanhf(lg) - (float)mask[b * C_ + c] * 1.0e8f;
        }
    }
}

// ---------------------------------------------------------------------------
extern "C" void kernel_launch(void* const* d_in, const int* in_sizes, int n_in,
                              void* d_out, int out_size) {
    const float* h    = (const float*)d_in[0];
    const float* hN   = (const float*)d_in[1];
    const float* hpr  = (const float*)d_in[2];
    const float* h0   = (const float*)d_in[3];
    const int*   mask = (const int*)  d_in[4];
    const float* Qw   = (const float*)d_in[5];
    const float* Qb   = (const float*)d_in[6];
    const float* Vw   = (const float*)d_in[7];
    const float* Vb   = (const float*)d_in[8];
    const float* Wow  = (const float*)d_in[9];
    const float* Wob  = (const float*)d_in[10];
    const float* Qfw  = (const float*)d_in[11];
    const float* Qfb  = (const float*)d_in[12];
    const float* Kfw  = (const float*)d_in[13];
    const float* Kfb  = (const float*)d_in[14];
    float* out = (float*)d_out;

    k_prep    <<<B_, 128>>>(hN, hpr, h0, Qw, Qb, Vw, Vb);
    k_fused   <<<dim3(SPLIT, B_), 256>>>(h, mask);
    k_epilogue<<<B_, 128>>>(Vw, Vb, Wow, Wob, Qfw, Qfb, Kfw, Kfb);
    k_logits  <<<dim3(4, B_), 256>>>(h, mask, out);
}

// round 6
// speedup vs baseline: 7.1036x; 1.0261x over previous
#include <cuda_runtime.h>
#include <math.h>

#define B_    1024
#define C_    1024
#define E_    128
#define SPLIT 4
#define RPB   (C_ / SPLIT)    // 256 rows per fused block
#define RPW   (RPB / 8)       // 32 rows per warp

// ---------------- device scratch (allocation-free rule) ----------------
__device__ float g_u [B_ * 8 * E_];          // per-batch per-head score vectors (0.25 folded)
__device__ float g_qb[B_ * 8];               // per-head score bias (0.25 folded)
__device__ float g_pl[B_ * SPLIT * 8];       // partial sum-exp
__device__ float g_ps[(size_t)B_ * SPLIT * 8 * E_];  // partial weighted h sums
__device__ float g_w [B_ * E_];              // logits matvec vector
__device__ float g_kb[B_];                   // logits scalar bias

// ---------------- f32x2 helpers (sm_103 packed fp32) ----------------
__device__ __forceinline__ unsigned long long pk2(float x, float y) {
    unsigned long long r;
    asm("mov.b64 %0, {%1, %2};" : "=l"(r) : "f"(x), "f"(y));
    return r;
}
__device__ __forceinline__ float2 upk2(unsigned long long v) {
    float2 r;
    asm("mov.b64 {%0, %1}, %2;" : "=f"(r.x), "=f"(r.y) : "l"(v));
    return r;
}
#define MUL2(d, a, b) asm("mul.rn.f32x2 %0, %1, %2;" : "=l"(d) : "l"(a), "l"(b))
#define FMA2(d, a, b) asm("fma.rn.f32x2 %0, %1, %2, %0;" : "+l"(d) : "l"(a), "l"(b))

// ---------------------------------------------------------------------------
// K0: per batch — q = Qw@hc + Qb;  u[h][:] = 0.25 * q_h^T Vw_h ;  qb[h] = 0.25 q_h.Vb_h
// ---------------------------------------------------------------------------
__global__ void __launch_bounds__(128) k_prep(
    const float* __restrict__ hN, const float* __restrict__ hpr,
    const float* __restrict__ h0,
    const float* __restrict__ Qw, const float* __restrict__ Qb,
    const float* __restrict__ Vw, const float* __restrict__ Vb)
{
    const int b = blockIdx.x, tid = threadIdx.x;
    __shared__ float hc_s[384];
    __shared__ float q_s[128];

    hc_s[tid]       = hN [b * E_ + tid];
    hc_s[128 + tid] = hpr[b * E_ + tid];
    hc_s[256 + tid] = h0 [b * E_ + tid];
    __syncthreads();

    {
        float a = Qb[tid];
        const float4* qr = (const float4*)(Qw + (size_t)tid * 384);
        const float4* xc = (const float4*)hc_s;
        #pragma unroll 8
        for (int i = 0; i < 96; i++) {
            float4 w = qr[i], x = xc[i];
            a += w.x * x.x + w.y * x.y + w.z * x.z + w.w * x.w;
        }
        q_s[tid] = a;
    }
    __syncthreads();

    const int k = tid;
    #pragma unroll
    for (int hh = 0; hh < 8; hh++) {
        float acc = 0.0f;
        #pragma unroll
        for (int j = 0; j < 16; j++)
            acc += q_s[hh * 16 + j] * Vw[(size_t)(hh * 16 + j) * E_ + k];
        g_u[((size_t)b * 8 + hh) * E_ + k] = 0.25f * acc;
    }
    if (tid < 8) {
        float a = 0.0f;
        #pragma unroll
        for (int j = 0; j < 16; j++)
            a += q_s[tid * 16 + j] * Vb[tid * 16 + j];
        g_qb[b * 8 + tid] = 0.25f * a;
    }
}

// ---------------------------------------------------------------------------
// K1: streaming dots + exp (no max shift) + weighted sums. Warp-independent.
//     f32x2 packed math, smem p-broadcast, 3-deep prefetch.
// ---------------------------------------------------------------------------
__global__ void __launch_bounds__(256) k_fused(const float* __restrict__ h,
                                               const int*   __restrict__ mask)
{
    const int b = blockIdx.y, part = blockIdx.x;
    const int tid = threadIdx.x, warp = tid >> 5, lane = tid & 31;

    // u slices packed: u01/u23[h] hold (u[e0],u[e1]) / (u[e2],u[e3]) for lane's e-slice
    unsigned long long u01[8], u23[8];
    #pragma unroll
    for (int hh = 0; hh < 8; hh++) {
        float4 uu = *(const float4*)&g_u[((size_t)b * 8 + hh) * E_ + lane * 4];
        u01[hh] = pk2(uu.x, uu.y);
        u23[hh] = pk2(uu.z, uu.w);
    }
    const float qbr = g_qb[b * 8 + (lane >> 2)];

    unsigned long long s2[16];          // s[h] as 2 packed pairs
    #pragma unroll
    for (int i = 0; i < 16; i++) s2[i] = pk2(0.f, 0.f);
    float l_acc = 0.0f;

    __shared__ float p_s[8][8];         // per-warp head probs

    const float* rp = h + ((size_t)b * C_ + part * RPB + warp) * E_ + lane * 4;
    const int*   mp = mask + b * C_ + part * RPB + warp;
    const size_t rs = (size_t)8 * E_;

    float4 f0 = *(const float4*)rp;
    float4 f1 = *(const float4*)(rp + rs);
    float4 f2 = *(const float4*)(rp + 2 * rs);
    int m0 = mp[0], m1 = mp[8], m2 = mp[16];

    const bool hi4 = (lane & 16) != 0;
    const bool hi3 = (lane & 8)  != 0;
    const bool hi2 = (lane & 4)  != 0;

    #pragma unroll 2
    for (int i = 0; i < RPW; i++) {
        float4 cur = f0; int mc = m0;
        f0 = f1; f1 = f2; m0 = m1; m1 = m2;
        if (i < RPW - 3) {
            f2 = *(const float4*)(rp + (size_t)(i + 3) * rs);
            m2 = mp[(i + 3) * 8];
        }

        unsigned long long cxy = pk2(cur.x, cur.y);
        unsigned long long czw = pk2(cur.z, cur.w);

        // packed partial dots: d[h] = lane's 4-elem dot for head h
        float d[8];
        #pragma unroll
        for (int hh = 0; hh < 8; hh++) {
            unsigned long long t;
            MUL2(t, cxy, u01[hh]);
            FMA2(t, czw, u23[hh]);
            float2 tt = upk2(t);
            d[hh] = tt.x + tt.y;
        }

        // head-folding butterfly: 9 shfl, lane ends with head (lane>>2)
        #pragma unroll
        for (int j = 0; j < 4; j++) {
            float send = hi4 ? d[j] : d[j + 4];
            float keep = hi4 ? d[j + 4] : d[j];
            d[j] = keep + __shfl_xor_sync(0xffffffffu, send, 16);
        }
        #pragma unroll
        for (int j = 0; j < 2; j++) {
            float send = hi3 ? d[j] : d[j + 2];
            float keep = hi3 ? d[j + 2] : d[j];
            d[j] = keep + __shfl_xor_sync(0xffffffffu, send, 8);
        }
        float send = hi2 ? d[0] : d[1];
        float keep = hi2 ? d[1] : d[0];
        float dd = keep + __shfl_xor_sync(0xffffffffu, send, 4);
        dd += __shfl_xor_sync(0xffffffffu, dd, 2);
        dd += __shfl_xor_sync(0xffffffffu, dd, 1);

        // p for this lane's head (shift-free exp: masked -> exact 0 underflow)
        float p = __expf(dd + qbr - (float)mc * 1.0e8f);
        l_acc += p;

        // broadcast 8 head probs via per-warp smem
        __syncwarp();
        if ((lane & 3) == 0) p_s[warp][lane >> 2] = p;
        __syncwarp();
        float4 pa = *(const float4*)&p_s[warp][0];
        float4 pb = *(const float4*)&p_s[warp][4];

        unsigned long long pd;
        pd = pk2(pa.x, pa.x); FMA2(s2[0],  cxy, pd); FMA2(s2[1],  czw, pd);
        pd = pk2(pa.y, pa.y); FMA2(s2[2],  cxy, pd); FMA2(s2[3],  czw, pd);
        pd = pk2(pa.z, pa.z); FMA2(s2[4],  cxy, pd); FMA2(s2[5],  czw, pd);
        pd = pk2(pa.w, pa.w); FMA2(s2[6],  cxy, pd); FMA2(s2[7],  czw, pd);
        pd = pk2(pb.x, pb.x); FMA2(s2[8],  cxy, pd); FMA2(s2[9],  czw, pd);
        pd = pk2(pb.y, pb.y); FMA2(s2[10], cxy, pd); FMA2(s2[11], czw, pd);
        pd = pk2(pb.z, pb.z); FMA2(s2[12], cxy, pd); FMA2(s2[13], czw, pd);
        pd = pk2(pb.w, pb.w); FMA2(s2[14], cxy, pd); FMA2(s2[15], czw, pd);
    }

    // combine 8 warps
    __shared__ float sm[8 * 8 * 128];     // [warp][h][e] = 32 KB
    __shared__ float sl[8][8];
    #pragma unroll
    for (int hh = 0; hh < 8; hh++) {
        float2 e01 = upk2(s2[2 * hh]);
        float2 e23 = upk2(s2[2 * hh + 1]);
        *(float4*)&sm[warp * 1024 + hh * 128 + lane * 4] =
            make_float4(e01.x, e01.y, e23.x, e23.y);
    }
    if ((lane & 3) == 0) sl[warp][lane >> 2] = l_acc;
    __syncthreads();

    const size_t base = (size_t)(b * SPLIT + part) * 8 * E_;
    #pragma unroll
    for (int k = 0; k < 4; k++) {
        int idx = tid + k * 256;
        float a = 0.0f;
        #pragma unroll
        for (int w = 0; w < 8; w++) a += sm[w * 1024 + idx];
        g_ps[base + idx] = a;
    }
    if (tid < 8) {
        float a = 0.0f;
        #pragma unroll
        for (int w = 0; w < 8; w++) a += sl[w][tid];
        g_pl[(b * SPLIT + part) * 8 + tid] = a;
    }
}

// ---------------------------------------------------------------------------
// K2: per batch — combine partials -> sbar -> ctx -> dec -> qf -> (w, kb)
// ---------------------------------------------------------------------------
__global__ void __launch_bounds__(128) k_epilogue(
    const float* __restrict__ Vw,  const float* __restrict__ Vb,
    const float* __restrict__ Wow, const float* __restrict__ Wob,
    const float* __restrict__ Qfw, const float* __restrict__ Qfb,
    const float* __restrict__ Kfw, const float* __restrict__ Kfb)
{
    const int b = blockIdx.x, tid = threadIdx.x;
    __shared__ float sbar[1024], ctx[128], dec[128], qf[128], r2[128];
    __shared__ float invl[8];

    if (tid < 8) {
        float L = 0.0f;
        #pragma unroll
        for (int p = 0; p < SPLIT; p++)
            L += g_pl[(b * SPLIT + p) * 8 + tid];
        invl[tid] = 1.0f / L;
    }
    __syncthreads();

    #pragma unroll
    for (int hh = 0; hh < 8; hh++) {
        float a = 0.0f;
        #pragma unroll
        for (int p = 0; p < SPLIT; p++)
            a += g_ps[(size_t)(b * SPLIT + p) * 8 * E_ + hh * E_ + tid];
        sbar[hh * 128 + tid] = a * invl[hh];
    }
    __syncthreads();

    // ctx[j] = sbar[head(j)] . Vw[j,:] + Vb[j]
    {
        const int head = tid >> 4;
        float a = Vb[tid];
        const float4* wr = (const float4*)(Vw + (size_t)tid * E_);
        const float4* xc = (const float4*)&sbar[head * 128];
        #pragma unroll 8
        for (int i = 0; i < 32; i++) {
            float4 w = wr[i], x = xc[i];
            a += w.x * x.x + w.y * x.y + w.z * x.z + w.w * x.w;
        }
        ctx[tid] = a;
    }
    __syncthreads();
    {
        float a = Wob[tid];
        const float4* wr = (const float4*)(Wow + (size_t)tid * E_);
        const float4* xc = (const float4*)ctx;
        #pragma unroll 8
        for (int i = 0; i < 32; i++) {
            float4 w = wr[i], x = xc[i];
            a += w.x * x.x + w.y * x.y + w.z * x.z + w.w * x.w;
        }
        dec[tid] = a;
    }
    __syncthreads();
    {
        float a = Qfb[tid];
        const float4* wr = (const float4*)(Qfw + (size_t)tid * E_);
        const float4* xc = (const float4*)dec;
        #pragma unroll 8
        for (int i = 0; i < 32; i++) {
            float4 w = wr[i], x = xc[i];
            a += w.x * x.x + w.y * x.y + w.z * x.z + w.w * x.w;
        }
        qf[tid] = a;
    }
    __syncthreads();

    {   // w[k] = sum_j qf[j] * Kfw[j][k]
        float a = 0.0f;
        #pragma unroll 8
        for (int j = 0; j < 128; j++)
            a += qf[j] * Kfw[(size_t)j * E_ + tid];
        g_w[b * 128 + tid] = a;
    }
    r2[tid] = qf[tid] * Kfb[tid];
    __syncthreads();
    for (int st = 64; st; st >>= 1) {
        if (tid < st) r2[tid] += r2[tid + st];
        __syncthreads();
    }
    if (tid == 0) g_kb[b] = r2[0];
}

// ---------------------------------------------------------------------------
// K3: logits[b][c] = 10*tanh((h.w + kb)/sqrt(E)) - mask*1e8  (paired-row fold)
// ---------------------------------------------------------------------------
__global__ void __launch_bounds__(256) k_logits(
    const float* __restrict__ h, const int* __restrict__ mask,
    float* __restrict__ out)
{
    const int b = blockIdx.y, chunk = blockIdx.x;
    const int warp = threadIdx.x >> 5, lane = threadIdx.x & 31;

    float4 w4 = *(const float4*)&g_w[b * 128 + lane * 4];
    float  kb = g_kb[b];

    const int c0 = chunk * 256 + warp * 32;       // warp handles 32 rows (16 pairs)
    const float* rp = h + ((size_t)b * C_ + c0) * E_ + lane * 4;
    const bool hi = (lane & 16) != 0;
    const int  sub = lane >> 4;                   // 0 -> even row, 1 -> odd row

    float4 a0 = *(const float4*)rp;
    float4 a1 = *(const float4*)(rp + E_);

    #pragma unroll 2
    for (int j = 0; j < 16; j++) {
        float4 r0 = a0, r1 = a1;
        if (j < 15) {
            a0 = *(const float4*)(rp + (size_t)(2 * j + 2) * E_);
            a1 = *(const float4*)(rp + (size_t)(2 * j + 3) * E_);
        }
        float p0 = r0.x * w4.x + r0.y * w4.y + r0.z * w4.z + r0.w * w4.w;
        float p1 = r1.x * w4.x + r1.y * w4.y + r1.z * w4.z + r1.w * w4.w;

        float send = hi ? p0 : p1;
        float keep = hi ? p1 : p0;
        float t = keep + __shfl_xor_sync(0xffffffffu, send, 16);
        t += __shfl_xor_sync(0xffffffffu, t, 8);
        t += __shfl_xor_sync(0xffffffffu, t, 4);
        t += __shfl_xor_sync(0xffffffffu, t, 2);
        t += __shfl_xor_sync(0xffffffffu, t, 1);

        if ((lane & 15) == 0) {
            int c = c0 + 2 * j + sub;
            float lg = (t + kb) * 0.08838834764831845f;   // 1/sqrt(128)
            out[(size_t)b * C_ + c] =
                10.0f * tanhf(lg) - (float)mask[b * C_ + c] * 1.0e8f;
        }
    }
}

// ---------------------------------------------------------------------------
extern "C" void kernel_launch(void* const* d_in, const int* in_sizes, int n_in,
                              void* d_out, int out_size) {
    const float* h    = (const float*)d_in[0];
    const float* hN   = (const float*)d_in[1];
    const float* hpr  = (const float*)d_in[2];
    const float* h0   = (const float*)d_in[3];
    const int*   mask = (const int*)  d_in[4];
    const float* Qw   = (const float*)d_in[5];
    const float* Qb   = (const float*)d_in[6];
    const float* Vw   = (const float*)d_in[7];
    const float* Vb   = (const float*)d_in[8];
    const float* Wow  = (const float*)d_in[9];
    const float* Wob  = (const float*)d_in[10];
    const float* Qfw  = (const float*)d_in[11];
    const float* Qfb  = (const float*)d_in[12];
    const float* Kfw  = (const float*)d_in[13];
    const float* Kfb  = (const float*)d_in[14];
    float* out = (float*)d_out;

    k_prep    <<<B_, 128>>>(hN, hpr, h0, Qw, Qb, Vw, Vb);
    k_fused   <<<dim3(SPLIT, B_), 256>>>(h, mask);
    k_epilogue<<<B_, 128>>>(Vw, Vb, Wow, Wob, Qfw, Qfb, Kfw, Kfb);
    k_logits  <<<dim3(4, B_), 256>>>(h, mask, out);
}

// round 7
// speedup vs baseline: 7.5889x; 1.0683x over previous
#include <cuda_runtime.h>
#include <math.h>

#define B_    1024
#define C_    1024
#define E_    128
#define SPLIT 4
#define RPB   (C_ / SPLIT)    // 256 rows per fused block
#define RPW   (RPB / 8)       // 32 rows per warp
#define NGRP  (RPW / 4)       // 8 groups of 4 rows

// ---------------- device scratch (allocation-free rule) ----------------
__device__ float g_u [B_ * 8 * E_];          // per-batch per-head score vectors (0.25 folded)
__device__ float g_qb[B_ * 8];               // per-head score bias (0.25 folded)
__device__ float g_pl[B_ * SPLIT * 8];       // partial sum-exp
__device__ float g_ps[(size_t)B_ * SPLIT * 8 * E_];  // partial weighted h sums
__device__ float g_w [B_ * E_];              // logits matvec vector
__device__ float g_kb[B_];                   // logits scalar bias

// ---------------- f32x2 helpers (sm_103 packed fp32) ----------------
__device__ __forceinline__ unsigned long long pk2(float x, float y) {
    unsigned long long r;
    asm("mov.b64 %0, {%1, %2};" : "=l"(r) : "f"(x), "f"(y));
    return r;
}
__device__ __forceinline__ float2 upk2(unsigned long long v) {
    float2 r;
    asm("mov.b64 {%0, %1}, %2;" : "=f"(r.x), "=f"(r.y) : "l"(v));
    return r;
}
#define MUL2(d, a, b) asm("mul.rn.f32x2 %0, %1, %2;" : "=l"(d) : "l"(a), "l"(b))
#define FMA2(d, a, b) asm("fma.rn.f32x2 %0, %1, %2, %0;" : "+l"(d) : "l"(a), "l"(b))

// ---------------------------------------------------------------------------
// K0: per batch — q = Qw@hc + Qb;  u[h][:] = 0.25 * q_h^T Vw_h ;  qb[h] = 0.25 q_h.Vb_h
// ---------------------------------------------------------------------------
__global__ void __launch_bounds__(128) k_prep(
    const float* __restrict__ hN, const float* __restrict__ hpr,
    const float* __restrict__ h0,
    const float* __restrict__ Qw, const float* __restrict__ Qb,
    const float* __restrict__ Vw, const float* __restrict__ Vb)
{
    const int b = blockIdx.x, tid = threadIdx.x;
    __shared__ float hc_s[384];
    __shared__ float q_s[128];

    hc_s[tid]       = hN [b * E_ + tid];
    hc_s[128 + tid] = hpr[b * E_ + tid];
    hc_s[256 + tid] = h0 [b * E_ + tid];
    __syncthreads();

    {
        float a = Qb[tid];
        const float4* qr = (const float4*)(Qw + (size_t)tid * 384);
        const float4* xc = (const float4*)hc_s;
        #pragma unroll 8
        for (int i = 0; i < 96; i++) {
            float4 w = qr[i], x = xc[i];
            a += w.x * x.x + w.y * x.y + w.z * x.z + w.w * x.w;
        }
        q_s[tid] = a;
    }
    __syncthreads();

    const int k = tid;
    #pragma unroll
    for (int hh = 0; hh < 8; hh++) {
        float acc = 0.0f;
        #pragma unroll
        for (int j = 0; j < 16; j++)
            acc += q_s[hh * 16 + j] * Vw[(size_t)(hh * 16 + j) * E_ + k];
        g_u[((size_t)b * 8 + hh) * E_ + k] = 0.25f * acc;
    }
    if (tid < 8) {
        float a = 0.0f;
        #pragma unroll
        for (int j = 0; j < 16; j++)
            a += q_s[tid * 16 + j] * Vb[tid * 16 + j];
        g_qb[b * 8 + tid] = 0.25f * a;
    }
}

// ---------------------------------------------------------------------------
// K1: streaming dots + exp + weighted sums, 4 rows per warp-iteration for ILP.
// ---------------------------------------------------------------------------
__global__ void __launch_bounds__(256) k_fused(const float* __restrict__ h,
                                               const int*   __restrict__ mask)
{
    const int b = blockIdx.y, part = blockIdx.x;
    const int tid = threadIdx.x, warp = tid >> 5, lane = tid & 31;

    unsigned long long u01[8], u23[8];
    #pragma unroll
    for (int hh = 0; hh < 8; hh++) {
        float4 uu = *(const float4*)&g_u[((size_t)b * 8 + hh) * E_ + lane * 4];
        u01[hh] = pk2(uu.x, uu.y);
        u23[hh] = pk2(uu.z, uu.w);
    }
    const float qbr = g_qb[b * 8 + (lane >> 2)];

    unsigned long long s2[16];          // s[h] as 2 packed pairs
    #pragma unroll
    for (int i = 0; i < 16; i++) s2[i] = pk2(0.f, 0.f);
    float l_acc = 0.0f;

    __shared__ float p_s[8][4][8];      // [warp][row-in-group][head]

    const float* rp = h + ((size_t)b * C_ + part * RPB + warp) * E_ + lane * 4;
    const int*   mp = mask + b * C_ + part * RPB + warp;
    const size_t rs = (size_t)8 * E_;

    const bool hi4 = (lane & 16) != 0;
    const bool hi3 = (lane & 8)  != 0;
    const bool hi2 = (lane & 4)  != 0;

    float4 cur[4]; int mc[4];
    #pragma unroll
    for (int j = 0; j < 4; j++) {
        cur[j] = *(const float4*)(rp + (size_t)j * rs);
        mc[j]  = mp[j * 8];
    }

    #pragma unroll 1
    for (int g = 0; g < NGRP; g++) {
        float4 nx[4]; int mn_[4];
        if (g < NGRP - 1) {
            #pragma unroll
            for (int j = 0; j < 4; j++) {
                nx[j]  = *(const float4*)(rp + (size_t)((g + 1) * 4 + j) * rs);
                mn_[j] = mp[((g + 1) * 4 + j) * 8];
            }
        }

        unsigned long long cxy[4], czw[4];
        #pragma unroll
        for (int j = 0; j < 4; j++) {
            cxy[j] = pk2(cur[j].x, cur[j].y);
            czw[j] = pk2(cur[j].z, cur[j].w);
        }

        // packed partial dots for 4 rows x 8 heads
        float d[4][8];
        #pragma unroll
        for (int j = 0; j < 4; j++)
            #pragma unroll
            for (int hh = 0; hh < 8; hh++) {
                unsigned long long t;
                MUL2(t, cxy[j], u01[hh]);
                FMA2(t, czw[j], u23[hh]);
                float2 tt = upk2(t);
                d[j][hh] = tt.x + tt.y;
            }

        // folds, level-major (4 independent chains in flight)
        #pragma unroll
        for (int j = 0; j < 4; j++)
            #pragma unroll
            for (int t = 0; t < 4; t++) {
                float send = hi4 ? d[j][t] : d[j][t + 4];
                float keep = hi4 ? d[j][t + 4] : d[j][t];
                d[j][t] = keep + __shfl_xor_sync(0xffffffffu, send, 16);
            }
        #pragma unroll
        for (int j = 0; j < 4; j++)
            #pragma unroll
            for (int t = 0; t < 2; t++) {
                float send = hi3 ? d[j][t] : d[j][t + 2];
                float keep = hi3 ? d[j][t + 2] : d[j][t];
                d[j][t] = keep + __shfl_xor_sync(0xffffffffu, send, 8);
            }
        float dd[4];
        #pragma unroll
        for (int j = 0; j < 4; j++) {
            float send = hi2 ? d[j][0] : d[j][1];
            float keep = hi2 ? d[j][1] : d[j][0];
            dd[j] = keep + __shfl_xor_sync(0xffffffffu, send, 4);
        }
        #pragma unroll
        for (int j = 0; j < 4; j++)
            dd[j] += __shfl_xor_sync(0xffffffffu, dd[j], 2);
        #pragma unroll
        for (int j = 0; j < 4; j++)
            dd[j] += __shfl_xor_sync(0xffffffffu, dd[j], 1);

        // exp (shift-free: masked rows underflow to exact 0)
        float p[4];
        #pragma unroll
        for (int j = 0; j < 4; j++) {
            p[j] = __expf(dd[j] + qbr - (float)mc[j] * 1.0e8f);
            l_acc += p[j];
        }

        __syncwarp();
        if ((lane & 3) == 0) {
            const int k = lane >> 2;
            #pragma unroll
            for (int j = 0; j < 4; j++) p_s[warp][j][k] = p[j];
        }
        __syncwarp();

        #pragma unroll
        for (int j = 0; j < 4; j++) {
            float4 pa = *(const float4*)&p_s[warp][j][0];
            float4 pb = *(const float4*)&p_s[warp][j][4];
            unsigned long long pd;
            pd = pk2(pa.x, pa.x); FMA2(s2[0],  cxy[j], pd); FMA2(s2[1],  czw[j], pd);
            pd = pk2(pa.y, pa.y); FMA2(s2[2],  cxy[j], pd); FMA2(s2[3],  czw[j], pd);
            pd = pk2(pa.z, pa.z); FMA2(s2[4],  cxy[j], pd); FMA2(s2[5],  czw[j], pd);
            pd = pk2(pa.w, pa.w); FMA2(s2[6],  cxy[j], pd); FMA2(s2[7],  czw[j], pd);
            pd = pk2(pb.x, pb.x); FMA2(s2[8],  cxy[j], pd); FMA2(s2[9],  czw[j], pd);
            pd = pk2(pb.y, pb.y); FMA2(s2[10], cxy[j], pd); FMA2(s2[11], czw[j], pd);
            pd = pk2(pb.z, pb.z); FMA2(s2[12], cxy[j], pd); FMA2(s2[13], czw[j], pd);
            pd = pk2(pb.w, pb.w); FMA2(s2[14], cxy[j], pd); FMA2(s2[15], czw[j], pd);
        }

        #pragma unroll
        for (int j = 0; j < 4; j++) { cur[j] = nx[j]; mc[j] = mn_[j]; }
    }

    // combine 8 warps
    __shared__ float sm[8 * 8 * 128];     // [warp][h][e] = 32 KB
    __shared__ float sl[8][8];
    #pragma unroll
    for (int hh = 0; hh < 8; hh++) {
        float2 e01 = upk2(s2[2 * hh]);
        float2 e23 = upk2(s2[2 * hh + 1]);
        *(float4*)&sm[warp * 1024 + hh * 128 + lane * 4] =
            make_float4(e01.x, e01.y, e23.x, e23.y);
    }
    if ((lane & 3) == 0) sl[warp][lane >> 2] = l_acc;
    __syncthreads();

    const size_t base = (size_t)(b * SPLIT + part) * 8 * E_;
    #pragma unroll
    for (int k = 0; k < 4; k++) {
        int idx = tid + k * 256;
        float a = 0.0f;
        #pragma unroll
        for (int w = 0; w < 8; w++) a += sm[w * 1024 + idx];
        g_ps[base + idx] = a;
    }
    if (tid < 8) {
        float a = 0.0f;
        #pragma unroll
        for (int w = 0; w < 8; w++) a += sl[w][tid];
        g_pl[(b * SPLIT + part) * 8 + tid] = a;
    }
}

// ---------------------------------------------------------------------------
// K2: per batch — combine partials -> sbar -> ctx -> dec -> qf -> (w, kb)
// ---------------------------------------------------------------------------
__global__ void __launch_bounds__(128) k_epilogue(
    const float* __restrict__ Vw,  const float* __restrict__ Vb,
    const float* __restrict__ Wow, const float* __restrict__ Wob,
    const float* __restrict__ Qfw, const float* __restrict__ Qfb,
    const float* __restrict__ Kfw, const float* __restrict__ Kfb)
{
    const int b = blockIdx.x, tid = threadIdx.x;
    __shared__ float sbar[1024], ctx[128], dec[128], qf[128], r2[128];
    __shared__ float invl[8];

    if (tid < 8) {
        float L = 0.0f;
        #pragma unroll
        for (int p = 0; p < SPLIT; p++)
            L += g_pl[(b * SPLIT + p) * 8 + tid];
        invl[tid] = 1.0f / L;
    }
    __syncthreads();

    #pragma unroll
    for (int hh = 0; hh < 8; hh++) {
        float a = 0.0f;
        #pragma unroll
        for (int p = 0; p < SPLIT; p++)
            a += g_ps[(size_t)(b * SPLIT + p) * 8 * E_ + hh * E_ + tid];
        sbar[hh * 128 + tid] = a * invl[hh];
    }
    __syncthreads();

    {
        const int head = tid >> 4;
        float a = Vb[tid];
        const float4* wr = (const float4*)(Vw + (size_t)tid * E_);
        const float4* xc = (const float4*)&sbar[head * 128];
        #pragma unroll 8
        for (int i = 0; i < 32; i++) {
            float4 w = wr[i], x = xc[i];
            a += w.x * x.x + w.y * x.y + w.z * x.z + w.w * x.w;
        }
        ctx[tid] = a;
    }
    __syncthreads();
    {
        float a = Wob[tid];
        const float4* wr = (const float4*)(Wow + (size_t)tid * E_);
        const float4* xc = (const float4*)ctx;
        #pragma unroll 8
        for (int i = 0; i < 32; i++) {
            float4 w = wr[i], x = xc[i];
            a += w.x * x.x + w.y * x.y + w.z * x.z + w.w * x.w;
        }
        dec[tid] = a;
    }
    __syncthreads();
    {
        float a = Qfb[tid];
        const float4* wr = (const float4*)(Qfw + (size_t)tid * E_);
        const float4* xc = (const float4*)dec;
        #pragma unroll 8
        for (int i = 0; i < 32; i++) {
            float4 w = wr[i], x = xc[i];
            a += w.x * x.x + w.y * x.y + w.z * x.z + w.w * x.w;
        }
        qf[tid] = a;
    }
    __syncthreads();

    {
        float a = 0.0f;
        #pragma unroll 8
        for (int j = 0; j < 128; j++)
            a += qf[j] * Kfw[(size_t)j * E_ + tid];
        g_w[b * 128 + tid] = a;
    }
    r2[tid] = qf[tid] * Kfb[tid];
    __syncthreads();
    for (int st = 64; st; st >>= 1) {
        if (tid < st) r2[tid] += r2[tid + st];
        __syncthreads();
    }
    if (tid == 0) g_kb[b] = r2[0];
}

// ---------------------------------------------------------------------------
// K3: logits[b][c] = 10*tanh((h.w + kb)/sqrt(E)) - mask*1e8  (paired-row fold)
// ---------------------------------------------------------------------------
__global__ void __launch_bounds__(256) k_logits(
    const float* __restrict__ h, const int* __restrict__ mask,
    float* __restrict__ out)
{
    const int b = blockIdx.y, chunk = blockIdx.x;
    const int warp = threadIdx.x >> 5, lane = threadIdx.x & 31;

    float4 w4 = *(const float4*)&g_w[b * 128 + lane * 4];
    float  kb = g_kb[b];

    const int c0 = chunk * 256 + warp * 32;
    const float* rp = h + ((size_t)b * C_ + c0) * E_ + lane * 4;
    const bool hi = (lane & 16) != 0;
    const int  sub = lane >> 4;

    float4 a0 = *(const float4*)rp;
    float4 a1 = *(const float4*)(rp + E_);

    #pragma unroll 2
    for (int j = 0; j < 16; j++) {
        float4 r0 = a0, r1 = a1;
        if (j < 15) {
            a0 = *(const float4*)(rp + (size_t)(2 * j + 2) * E_);
            a1 = *(const float4*)(rp + (size_t)(2 * j + 3) * E_);
        }
        float p0 = r0.x * w4.x + r0.y * w4.y + r0.z * w4.z + r0.w * w4.w;
        float p1 = r1.x * w4.x + r1.y * w4.y + r1.z * w4.z + r1.w * w4.w;

        float send = hi ? p0 : p1;
        float keep = hi ? p1 : p0;
        float t = keep + __shfl_xor_sync(0xffffffffu, send, 16);
        t += __shfl_xor_sync(0xffffffffu, t, 8);
        t += __shfl_xor_sync(0xffffffffu, t, 4);
        t += __shfl_xor_sync(0xffffffffu, t, 2);
        t += __shfl_xor_sync(0xffffffffu, t, 1);

        if ((lane & 15) == 0) {
            int c = c0 + 2 * j + sub;
            float lg = (t + kb) * 0.08838834764831845f;   // 1/sqrt(128)
            out[(size_t)b * C_ + c] =
                10.0f * tanhf(lg) - (float)mask[b * C_ + c] * 1.0e8f;
        }
    }
}

// ---------------------------------------------------------------------------
extern "C" void kernel_launch(void* const* d_in, const int* in_sizes, int n_in,
                              void* d_out, int out_size) {
    const float* h    = (const float*)d_in[0];
    const float* hN   = (const float*)d_in[1];
    const float* hpr  = (const float*)d_in[2];
    const float* h0   = (const float*)d_in[3];
    const int*   mask = (const int*)  d_in[4];
    const float* Qw   = (const float*)d_in[5];
    const float* Qb   = (const float*)d_in[6];
    const float* Vw   = (const float*)d_in[7];
    const float* Vb   = (const float*)d_in[8];
    const float* Wow  = (const float*)d_in[9];
    const float* Wob  = (const float*)d_in[10];
    const float* Qfw  = (const float*)d_in[11];
    const float* Qfb  = (const float*)d_in[12];
    const float* Kfw  = (const float*)d_in[13];
    const float* Kfb  = (const float*)d_in[14];
    float* out = (float*)d_out;

    k_prep    <<<B_, 128>>>(hN, hpr, h0, Qw, Qb, Vw, Vb);
    k_fused   <<<dim3(SPLIT, B_), 256>>>(h, mask);
    k_epilogue<<<B_, 128>>>(Vw, Vb, Wow, Wob, Qfw, Qfb, Kfw, Kfb);
    k_logits  <<<dim3(4, B_), 256>>>(h, mask, out);
}